// round 1
// baseline (speedup 1.0000x reference)
#include <cuda_runtime.h>
#include <cstdint>

#define Bc 16
#define Sc 512
#define Dc 768
#define Lc 20
#define INNERc 64
#define NEGF 1000000000000.0f

// ---------------- scratch (no allocation allowed) ----------------
__device__ float g_q[Bc * Sc * INNERc];    // 2 MB, RoPE'd q
__device__ float g_k[Bc * Sc * INNERc];    // 2 MB, RoPE'd k
__device__ float g_bn[Bc * Lc * Sc];       // dense[b,2l,n]/2  (added along n)
__device__ float g_bm[Bc * Lc * Sc];       // dense[b,2l+1,m]/2 (added along m)
__device__ float g_cos[Sc * 32];
__device__ float g_sin[Sc * 32];

// ---------------- kernel 0: RoPE tables (fp64 for accuracy) ----------------
__global__ void rope_tables_kernel() {
    int idx = blockIdx.x * blockDim.x + threadIdx.x;   // 16384 = 512*32
    int s = idx >> 5, i = idx & 31;
    // freq_i = 10000^(-2 i / 64) = 2^(-i * log2(1e4) / 32)
    double f = exp2(-(double)i * (13.287712379549449 / 32.0));
    double ang = (double)s * f;
    g_cos[idx] = (float)cos(ang);
    g_sin[idx] = (float)sin(ang);
}

// ---------------- f32x2 helpers ----------------
__device__ __forceinline__ unsigned long long fma2(unsigned long long a,
                                                   unsigned long long b,
                                                   unsigned long long c) {
    unsigned long long d;
    asm("fma.rn.f32x2 %0, %1, %2, %3;" : "=l"(d) : "l"(a), "l"(b), "l"(c));
    return d;
}
__device__ __forceinline__ unsigned long long bcast2(float w) {
    unsigned long long d;
    unsigned int u = __float_as_uint(w);
    asm("mov.b64 %0, {%1, %1};" : "=l"(d) : "r"(u));
    return d;
}

// ---------------- kernel 1: fused GEMM1+RoPE+bias-split  ||  constant writer ----
// blocks [0,256): GEMM1 rows (32 rows/block of the 8192 (b,s) rows)
// blocks [256,704): fully-causal-masked output tiles (tm>tn): constants only
__global__ void __launch_bounds__(256) phase1_fast_kernel(
    const float* __restrict__ x, const int* __restrict__ am,
    const float* __restrict__ w1, const float* __restrict__ b1,
    const float* __restrict__ w2, const float* __restrict__ b2,
    float* __restrict__ out)
{
    const size_t PROB_OFF = (size_t)Bc * Lc * Sc * Sc;   // 83886080
    int bid = blockIdx.x;
    int tid = threadIdx.x;

    if (bid >= 256) {
        // -------- fast path: tm > tn  => every element strictly below diagonal
        // logits = keep ? -NEG : -2*NEG  (exact, since |raw| << ulp(1e12));  probs = 0
        int f = bid - 256;               // 0..447
        int b = f / 28;
        int p = f % 28;
        int tm = 1;
        while (p >= tm) { p -= tm; tm++; }   // tm in 1..7, tn = p < tm
        int tn = p;
        int m0 = tm * 64, n0 = tn * 64;
        int tx = tid & 15, ty = tid >> 4;
        const int* amb = am + b * Sc;
        int gn = n0 + tx * 4;
        int mn0 = amb[gn + 0], mn1 = amb[gn + 1], mn2 = amb[gn + 2], mn3 = amb[gn + 3];
        float4 lv[4];
        #pragma unroll
        for (int i = 0; i < 4; i++) {
            int mmv = amb[m0 + ty * 4 + i];
            lv[i].x = (mmv && mn0) ? -NEGF : -2.0f * NEGF;
            lv[i].y = (mmv && mn1) ? -NEGF : -2.0f * NEGF;
            lv[i].z = (mmv && mn2) ? -NEGF : -2.0f * NEGF;
            lv[i].w = (mmv && mn3) ? -NEGF : -2.0f * NEGF;
        }
        float4 z4 = make_float4(0.f, 0.f, 0.f, 0.f);
        for (int l = 0; l < Lc; l++) {
            #pragma unroll
            for (int i = 0; i < 4; i++) {
                size_t o = (((size_t)(b * Lc + l)) * Sc + (m0 + ty * 4 + i)) * (size_t)Sc + gn;
                __stcs(reinterpret_cast<float4*>(out + o), lv[i]);
                __stcs(reinterpret_cast<float4*>(out + PROB_OFF + o), z4);
            }
        }
        return;
    }

    // -------- GEMM1: out1[8192 x 192pad] = x[8192 x 768] @ [w1|w2|0]
    __shared__ float xs[32][34];    // transposed tile: xs[kk][r]
    __shared__ float ws[32][192];   // ws[kk][c], c<128: w1, 128..167: w2, rest 0

    int row0 = bid * 32;
    int ct = tid & 31;        // col thread (lane)
    int rt = tid >> 5;        // row thread 0..7
    int r0 = rt * 4;          // 4 rows per thread, as 2 f32x2 pairs

    unsigned long long acc[2][6];
    #pragma unroll
    for (int a = 0; a < 2; a++)
        #pragma unroll
        for (int j = 0; j < 6; j++) acc[a][j] = 0ull;

    for (int k0 = 0; k0 < Dc; k0 += 32) {
        #pragma unroll
        for (int t = 0; t < 4; t++) {
            int idx = tid + t * 256;        // 1024 = 32x32
            int r = idx >> 5, kk = idx & 31;
            xs[kk][r] = x[(size_t)(row0 + r) * Dc + k0 + kk];
        }
        #pragma unroll
        for (int t = 0; t < 24; t++) {
            int idx = tid + t * 256;        // 6144 = 32x192
            int kk = idx / 192, c = idx - kk * 192;
            float v;
            if (c < 128)      v = w1[(size_t)(k0 + kk) * 128 + c];
            else if (c < 168) v = w2[(size_t)(k0 + kk) * 40 + (c - 128)];
            else              v = 0.f;
            ws[kk][c] = v;
        }
        __syncthreads();
        #pragma unroll
        for (int kk = 0; kk < 32; kk++) {
            unsigned long long xa = *reinterpret_cast<const unsigned long long*>(&xs[kk][r0]);
            unsigned long long xb = *reinterpret_cast<const unsigned long long*>(&xs[kk][r0 + 2]);
            #pragma unroll
            for (int j = 0; j < 6; j++) {
                unsigned long long wp = bcast2(ws[kk][ct + 32 * j]);
                acc[0][j] = fma2(xa, wp, acc[0][j]);
                acc[1][j] = fma2(xb, wp, acc[1][j]);
            }
        }
        __syncthreads();
    }

    // -------- epilogue: bias, RoPE (cross-lane pair via shfl.xor 2), scatter
    #pragma unroll
    for (int j = 0; j < 6; j++) {
        int c = ct + 32 * j;
        float bias = 0.f;
        if (c < 128)      bias = b1[c];
        else if (c < 168) bias = b2[c - 128];
        #pragma unroll
        for (int rr = 0; rr < 4; rr++) {
            unsigned long long a = acc[rr >> 1][j];
            unsigned int u = (rr & 1) ? (unsigned int)(a >> 32) : (unsigned int)a;
            float v = __uint_as_float(u) + bias;
            float prt = __shfl_xor_sync(0xffffffffu, v, 2);  // col c ^ 2 partner
            int row = row0 + r0 + rr;
            int bb = row >> 9, s = row & 511;
            if (c < 128) {
                int i = c >> 2;
                float cs = g_cos[(s << 5) + i];
                float sn = g_sin[(s << 5) + i];
                // even half of RoPE pair: v*cos - partner*sin ; odd: v*cos + partner*sin
                float o = (c & 2) ? (v * cs + prt * sn) : (v * cs - prt * sn);
                if (c & 1) g_k[(size_t)row * 64 + (c >> 1)] = o;
                else       g_q[(size_t)row * 64 + (c >> 1)] = o;
            } else if (c < 168) {
                int cc = c - 128;
                float val = v * 0.5f;
                int l = cc >> 1;
                size_t o = ((size_t)bb * Lc + l) * Sc + s;
                if (cc & 1) g_bm[o] = val;
                else        g_bn[o] = val;
            }
        }
    }
}

// ---------------- kernel 2: base q.k^T tile + 20 L-slices of fused epilogue ----
__global__ void __launch_bounds__(256) phase2_kernel(
    const int* __restrict__ am, float* __restrict__ out)
{
    int tn = blockIdx.x, tm = blockIdx.y, b = blockIdx.z;
    if (tm > tn) return;                     // fully-masked tiles handled in kernel 1

    __shared__ float qT[64][68];             // transposed: qT[kk][m]
    __shared__ float kT[64][68];
    __shared__ float bnS[Lc][64];
    __shared__ float bmS[Lc][64];
    __shared__ int   mMs[64], mNs[64];

    int tid = threadIdx.x;
    int m0 = tm * 64, n0 = tn * 64;
    const float* qb = g_q + (size_t)b * Sc * 64;
    const float* kb = g_k + (size_t)b * Sc * 64;

    #pragma unroll
    for (int t = 0; t < 16; t++) {
        int idx = tid + t * 256;             // 4096 = 64x64
        int r = idx >> 6, kk = idx & 63;
        qT[kk][r] = qb[(size_t)(m0 + r) * 64 + kk];
        kT[kk][r] = kb[(size_t)(n0 + r) * 64 + kk];
    }
    for (int idx = tid; idx < Lc * 64; idx += 256) {
        int l = idx >> 6, j = idx & 63;
        bnS[l][j] = g_bn[((size_t)b * Lc + l) * Sc + n0 + j];
        bmS[l][j] = g_bm[((size_t)b * Lc + l) * Sc + m0 + j];
    }
    if (tid < 64) {
        mMs[tid] = am[b * Sc + m0 + tid];
        mNs[tid] = am[b * Sc + n0 + tid];
    }
    __syncthreads();

    int tx = tid & 15, ty = tid >> 4;
    int nl = tx * 4, ml = ty * 4;

    float acc[4][4];
    #pragma unroll
    for (int i = 0; i < 4; i++)
        #pragma unroll
        for (int j = 0; j < 4; j++) acc[i][j] = 0.f;

    #pragma unroll 4
    for (int kk = 0; kk < 64; kk++) {
        float4 qv = *reinterpret_cast<const float4*>(&qT[kk][ml]);
        float4 kv = *reinterpret_cast<const float4*>(&kT[kk][nl]);
        float q4[4] = {qv.x, qv.y, qv.z, qv.w};
        float k4[4] = {kv.x, kv.y, kv.z, kv.w};
        #pragma unroll
        for (int i = 0; i < 4; i++)
            #pragma unroll
            for (int j = 0; j < 4; j++)
                acc[i][j] += q4[i] * k4[j];
    }
    #pragma unroll
    for (int i = 0; i < 4; i++)
        #pragma unroll
        for (int j = 0; j < 4; j++) acc[i][j] *= 0.125f;   // /sqrt(64), exact

    int mm[4], mn[4];
    #pragma unroll
    for (int i = 0; i < 4; i++) mm[i] = mMs[ml + i];
    #pragma unroll
    for (int j = 0; j < 4; j++) mn[j] = mNs[nl + j];

    float* probs = out + (size_t)Bc * Lc * Sc * Sc;
    int gn0 = n0 + nl;

    #pragma unroll 2
    for (int l = 0; l < Lc; l++) {
        float4 bn4 = *reinterpret_cast<const float4*>(&bnS[l][nl]);
        float bnv[4] = {bn4.x, bn4.y, bn4.z, bn4.w};
        #pragma unroll
        for (int i = 0; i < 4; i++) {
            int gm = m0 + ml + i;
            float bm = bmS[l][ml + i];
            float lv[4], pv[4];
            #pragma unroll
            for (int j = 0; j < 4; j++) {
                int gn = gn0 + j;
                float v = (mm[i] && mn[j]) ? ((acc[i][j] + bnv[j]) + bm) : -NEGF;
                if (gm > gn) v -= NEGF;                       // strict lower triangle
                float e = __expf(-v);
                float p = __fdividef(1.0f, 1.0f + e);
                lv[j] = v; pv[j] = p;
            }
            size_t o = (((size_t)(b * Lc + l)) * Sc + gm) * (size_t)Sc + gn0;
            __stcs(reinterpret_cast<float4*>(out + o),
                   make_float4(lv[0], lv[1], lv[2], lv[3]));
            __stcs(reinterpret_cast<float4*>(probs + o),
                   make_float4(pv[0], pv[1], pv[2], pv[3]));
        }
    }
}

// ---------------- launcher ----------------
extern "C" void kernel_launch(void* const* d_in, const int* in_sizes, int n_in,
                              void* d_out, int out_size) {
    (void)in_sizes; (void)n_in; (void)out_size;
    const float* x  = (const float*)d_in[0];
    const int*   am = (const int*)  d_in[1];
    const float* w1 = (const float*)d_in[2];
    const float* b1 = (const float*)d_in[3];
    const float* w2 = (const float*)d_in[4];
    const float* b2 = (const float*)d_in[5];
    float* out = (float*)d_out;

    rope_tables_kernel<<<32, 512>>>();
    phase1_fast_kernel<<<704, 256>>>(x, am, w1, b1, w2, b2, out);
    dim3 g2(8, 8, Bc);
    phase2_kernel<<<g2, 256>>>(am, out);
}

// round 4
// speedup vs baseline: 1.0766x; 1.0766x over previous
#include <cuda_runtime.h>
#include <cstdint>

#define Bc 16
#define Sc 512
#define Dc 768
#define Lc 20
#define INNERc 64
#define NEGF 1000000000000.0f

typedef unsigned long long ull;

// ---------------- scratch (no allocation allowed) ----------------
__device__ float g_q[Bc * Sc * INNERc];    // 2 MB, RoPE'd q, pre-scaled by 1/8 (exact)
__device__ float g_k[Bc * Sc * INNERc];    // 2 MB, RoPE'd k
__device__ float g_bn[Bc * Lc * Sc];       // dense[b,2l,n]/2  (added along n)
__device__ float g_bm[Bc * Lc * Sc];       // dense[b,2l+1,m]/2 (added along m)
__device__ float g_cos[Sc * 32];
__device__ float g_sin[Sc * 32];

// ---------------- f32x2 helpers ----------------
__device__ __forceinline__ ull fma2(ull a, ull b, ull c) {
    ull d;
    asm("fma.rn.f32x2 %0, %1, %2, %3;" : "=l"(d) : "l"(a), "l"(b), "l"(c));
    return d;
}
__device__ __forceinline__ ull add2(ull a, ull b) {
    ull d;
    asm("add.rn.f32x2 %0, %1, %2;" : "=l"(d) : "l"(a), "l"(b));
    return d;
}
__device__ __forceinline__ ull bcast2(float w) {
    ull d;
    unsigned int u = __float_as_uint(w);
    asm("mov.b64 %0, {%1, %1};" : "=l"(d) : "r"(u));
    return d;
}
__device__ __forceinline__ ull pack2(float lo, float hi) {
    ull d;
    asm("mov.b64 %0, {%1, %2};" : "=l"(d) : "f"(lo), "f"(hi));
    return d;
}
__device__ __forceinline__ void unpack2(ull v, float& lo, float& hi) {
    asm("mov.b64 {%0, %1}, %2;" : "=f"(lo), "=f"(hi) : "l"(v));
}
__device__ __forceinline__ float fast_sigmoid(float v) {
    float t;
    asm("tanh.approx.f32 %0, %1;" : "=f"(t) : "f"(v * 0.5f));
    return fmaf(t, 0.5f, 0.5f);
}

// ---------------- kernel 0: RoPE tables (fp32, wide grid) ----------------
__global__ void rope_tables_kernel() {
    int idx = blockIdx.x * blockDim.x + threadIdx.x;   // 16384 = 512*32
    int s = idx >> 5, i = idx & 31;
    // freq_i = 10000^(-2 i / 64) = 2^(-i * log2(1e4) / 32)
    float f = exp2f(-(float)i * 0.41524101186092036f);
    float ang = (float)s * f;
    float sv, cv;
    sincosf(ang, &sv, &cv);
    g_cos[idx] = cv;
    g_sin[idx] = sv;
}

// ---------------- kernel 1: fused GEMM1+RoPE+bias-split  ||  constant writer ----
// blocks [0,256): GEMM1 rows (32 rows/block of the 8192 (b,s) rows)
// blocks [256,704): fully-causal-masked output tiles (tm>tn): constants only
__global__ void __launch_bounds__(256) phase1_fast_kernel(
    const float* __restrict__ x, const int* __restrict__ am,
    const float* __restrict__ w1, const float* __restrict__ b1,
    const float* __restrict__ w2, const float* __restrict__ b2,
    float* __restrict__ out)
{
    const size_t PROB_OFF = (size_t)Bc * Lc * Sc * Sc;   // 83886080
    int bid = blockIdx.x;
    int tid = threadIdx.x;

    if (bid >= 256) {
        // -------- fast path: tm > tn => every element strictly below diagonal
        // logits = keep ? -NEG : -2*NEG  (exact: |raw| << ulp(1e12)); probs = 0
        int f = bid - 256;               // 0..447
        int b = f / 28;
        int p = f % 28;
        int tm = 1;
        while (p >= tm) { p -= tm; tm++; }   // tm in 1..7, tn = p < tm
        int tn = p;
        int m0 = tm * 64, n0 = tn * 64;
        int tx = tid & 15, ty = tid >> 4;
        const int* amb = am + b * Sc;
        int gn = n0 + tx * 4;
        int mn0 = amb[gn + 0], mn1 = amb[gn + 1], mn2 = amb[gn + 2], mn3 = amb[gn + 3];
        float4 lv[4];
        #pragma unroll
        for (int i = 0; i < 4; i++) {
            int mmv = amb[m0 + ty * 4 + i];
            lv[i].x = (mmv && mn0) ? -NEGF : -2.0f * NEGF;
            lv[i].y = (mmv && mn1) ? -NEGF : -2.0f * NEGF;
            lv[i].z = (mmv && mn2) ? -NEGF : -2.0f * NEGF;
            lv[i].w = (mmv && mn3) ? -NEGF : -2.0f * NEGF;
        }
        float4 z4 = make_float4(0.f, 0.f, 0.f, 0.f);
        float* p0 = out + (((size_t)(b * Lc)) * Sc + (m0 + ty * 4)) * (size_t)Sc + gn;
        for (int l = 0; l < Lc; l++) {
            #pragma unroll
            for (int i = 0; i < 4; i++) {
                float* pp = p0 + (size_t)i * Sc;
                __stcs(reinterpret_cast<float4*>(pp), lv[i]);
                __stcs(reinterpret_cast<float4*>(pp + PROB_OFF), z4);
            }
            p0 += (size_t)Sc * Sc;
        }
        return;
    }

    // -------- GEMM1: out1[8192 x 192pad] = x[8192 x 768] @ [w1|w2|0]
    __shared__ float xs[32][34];    // transposed tile: xs[kk][r]
    __shared__ float ws[32][192];   // ws[kk][c], c<128: w1, 128..167: w2, rest 0

    int row0 = bid * 32;
    int ct = tid & 31;        // col thread (lane)
    int rt = tid >> 5;        // row thread 0..7
    int r0 = rt * 4;          // 4 rows per thread, as 2 f32x2 pairs

    ull acc[2][6];
    #pragma unroll
    for (int a = 0; a < 2; a++)
        #pragma unroll
        for (int j = 0; j < 6; j++) acc[a][j] = 0ull;

    for (int k0 = 0; k0 < Dc; k0 += 32) {
        #pragma unroll
        for (int t = 0; t < 4; t++) {
            int idx = tid + t * 256;        // 1024 = 32x32
            int r = idx >> 5, kk = idx & 31;
            xs[kk][r] = x[(size_t)(row0 + r) * Dc + k0 + kk];
        }
        #pragma unroll
        for (int t = 0; t < 24; t++) {
            int idx = tid + t * 256;        // 6144 = 32x192
            int kk = idx / 192, c = idx - kk * 192;
            float v;
            if (c < 128)      v = w1[(size_t)(k0 + kk) * 128 + c];
            else if (c < 168) v = w2[(size_t)(k0 + kk) * 40 + (c - 128)];
            else              v = 0.f;
            ws[kk][c] = v;
        }
        __syncthreads();
        #pragma unroll
        for (int kk = 0; kk < 32; kk++) {
            ull xa = *reinterpret_cast<const ull*>(&xs[kk][r0]);
            ull xb = *reinterpret_cast<const ull*>(&xs[kk][r0 + 2]);
            #pragma unroll
            for (int j = 0; j < 6; j++) {
                ull wp = bcast2(ws[kk][ct + 32 * j]);
                acc[0][j] = fma2(xa, wp, acc[0][j]);
                acc[1][j] = fma2(xb, wp, acc[1][j]);
            }
        }
        __syncthreads();
    }

    // -------- epilogue: bias, RoPE (cross-lane pair via shfl.xor 2), scatter
    #pragma unroll
    for (int j = 0; j < 6; j++) {
        int c = ct + 32 * j;
        float bias = 0.f;
        if (c < 128)      bias = b1[c];
        else if (c < 168) bias = b2[c - 128];
        #pragma unroll
        for (int rr = 0; rr < 4; rr++) {
            ull a = acc[rr >> 1][j];
            unsigned int u = (rr & 1) ? (unsigned int)(a >> 32) : (unsigned int)a;
            float v = __uint_as_float(u) + bias;
            float prt = __shfl_xor_sync(0xffffffffu, v, 2);  // col c ^ 2 partner
            int row = row0 + r0 + rr;
            int bb = row >> 9, s = row & 511;
            if (c < 128) {
                int i = c >> 2;
                float cs = g_cos[(s << 5) + i];
                float sn = g_sin[(s << 5) + i];
                float o = (c & 2) ? (v * cs + prt * sn) : (v * cs - prt * sn);
                if (c & 1) g_k[(size_t)row * 64 + (c >> 1)] = o;
                else       g_q[(size_t)row * 64 + (c >> 1)] = o * 0.125f;  // /8 folded, exact
            } else if (c < 168) {
                int cc = c - 128;
                float val = v * 0.5f;
                int l = cc >> 1;
                size_t o = ((size_t)bb * Lc + l) * Sc + s;
                if (cc & 1) g_bm[o] = val;
                else        g_bn[o] = val;
            }
        }
    }
}

// ---------------- kernel 2: base q.k^T tile + 10 L-slices of fused epilogue ----
// grid: x = 36 upper-tri tiles * 2 l-halves, y = batch
__global__ void __launch_bounds__(256) phase2_kernel(
    const int* __restrict__ am, float* __restrict__ out)
{
    __shared__ float qT[64][68];             // transposed: qT[kk][m]
    __shared__ float kT[64][68];
    __shared__ float bnS[10][64];
    __shared__ float bmS[10][64];
    __shared__ int   mMs[64], mNs[64];

    int bx = blockIdx.x;
    int b = blockIdx.y;
    int lh = bx & 1, tidx = bx >> 1;
    int tm = 0;
    { int t = tidx; while (t >= 8 - tm) { t -= 8 - tm; tm++; } tidx = t; }
    int tn = tm + tidx;
    int l0 = lh * 10;

    int tid = threadIdx.x;
    int m0 = tm * 64, n0 = tn * 64;
    const float* qb = g_q + (size_t)b * Sc * 64;
    const float* kb = g_k + (size_t)b * Sc * 64;

    #pragma unroll
    for (int t = 0; t < 16; t++) {
        int idx = tid + t * 256;             // 4096 = 64x64
        int r = idx >> 6, kk = idx & 63;
        qT[kk][r] = qb[(size_t)(m0 + r) * 64 + kk];
        kT[kk][r] = kb[(size_t)(n0 + r) * 64 + kk];
    }
    for (int idx = tid; idx < 10 * 64; idx += 256) {
        int l = idx >> 6, j = idx & 63;
        bnS[l][j] = g_bn[((size_t)b * Lc + l0 + l) * Sc + n0 + j];
        bmS[l][j] = g_bm[((size_t)b * Lc + l0 + l) * Sc + m0 + j];
    }
    if (tid < 64) {
        mMs[tid] = am[b * Sc + m0 + tid];
        mNs[tid] = am[b * Sc + n0 + tid];
    }
    __syncthreads();

    int tx = tid & 15, ty = tid >> 4;
    int nl = tx * 4, ml = ty * 4;

    ull acc2[4][2];
    #pragma unroll
    for (int i = 0; i < 4; i++) { acc2[i][0] = 0ull; acc2[i][1] = 0ull; }

    #pragma unroll 4
    for (int kk = 0; kk < 64; kk++) {
        float4 qv = *reinterpret_cast<const float4*>(&qT[kk][ml]);
        ull k01 = *reinterpret_cast<const ull*>(&kT[kk][nl]);
        ull k23 = *reinterpret_cast<const ull*>(&kT[kk][nl + 2]);
        ull q0 = bcast2(qv.x), q1 = bcast2(qv.y), q2 = bcast2(qv.z), q3 = bcast2(qv.w);
        acc2[0][0] = fma2(q0, k01, acc2[0][0]); acc2[0][1] = fma2(q0, k23, acc2[0][1]);
        acc2[1][0] = fma2(q1, k01, acc2[1][0]); acc2[1][1] = fma2(q1, k23, acc2[1][1]);
        acc2[2][0] = fma2(q2, k01, acc2[2][0]); acc2[2][1] = fma2(q2, k23, acc2[2][1]);
        acc2[3][0] = fma2(q3, k01, acc2[3][0]); acc2[3][1] = fma2(q3, k23, acc2[3][1]);
    }
    // acc2 already = q.k / 8 (scale folded into g_q, exact power of 2)

    int mm[4], mn[4];
    #pragma unroll
    for (int i = 0; i < 4; i++) mm[i] = mMs[ml + i];
    #pragma unroll
    for (int j = 0; j < 4; j++) mn[j] = mNs[nl + j];

    float* probs = out + (size_t)Bc * Lc * Sc * Sc;
    int gm0 = m0 + ml, gn0 = n0 + nl;
    size_t rowbase = (((size_t)(b * Lc + l0)) * Sc + gm0) * (size_t)Sc + gn0;

    for (int l = 0; l < 10; l++) {
        float4 bnv = *reinterpret_cast<const float4*>(&bnS[l][nl]);
        ull bn01 = pack2(bnv.x, bnv.y);
        ull bn23 = pack2(bnv.z, bnv.w);
        #pragma unroll
        for (int i = 0; i < 4; i++) {
            int gm = gm0 + i;
            ull bm2 = bcast2(bmS[l][ml + i]);
            ull v01 = add2(add2(acc2[i][0], bn01), bm2);
            ull v23 = add2(add2(acc2[i][1], bn23), bm2);
            float v[4];
            unpack2(v01, v[0], v[1]);
            unpack2(v23, v[2], v[3]);
            float lv[4], pv[4];
            #pragma unroll
            for (int j = 0; j < 4; j++) {
                float xv = (mm[i] && mn[j]) ? v[j] : -NEGF;
                if (gm > gn0 + j) xv -= NEGF;       // strict lower triangle
                lv[j] = xv;
                pv[j] = fast_sigmoid(xv);
            }
            size_t o = rowbase + (size_t)i * Sc;
            __stcs(reinterpret_cast<float4*>(out + o),
                   make_float4(lv[0], lv[1], lv[2], lv[3]));
            __stcs(reinterpret_cast<float4*>(probs + o),
                   make_float4(pv[0], pv[1], pv[2], pv[3]));
        }
        rowbase += (size_t)Sc * Sc;
    }
}

// ---------------- launcher ----------------
extern "C" void kernel_launch(void* const* d_in, const int* in_sizes, int n_in,
                              void* d_out, int out_size) {
    (void)in_sizes; (void)n_in; (void)out_size;
    const float* x  = (const float*)d_in[0];
    const int*   am = (const int*)  d_in[1];
    const float* w1 = (const float*)d_in[2];
    const float* b1 = (const float*)d_in[3];
    const float* w2 = (const float*)d_in[4];
    const float* b2 = (const float*)d_in[5];
    float* out = (float*)d_out;

    rope_tables_kernel<<<64, 256>>>();
    phase1_fast_kernel<<<704, 256>>>(x, am, w1, b1, w2, b2, out);
    dim3 g2(72, 16);
    phase2_kernel<<<g2, 256>>>(am, out);
}

// round 6
// speedup vs baseline: 1.0930x; 1.0152x over previous
#include <cuda_runtime.h>
#include <cstdint>

#define Bc 16
#define Sc 512
#define Dc 768
#define Lc 20
#define INNERc 64
#define NEGF 1000000000000.0f

typedef unsigned long long ull;

// ---------------- scratch (no allocation allowed) ----------------
__device__ float g_q[Bc * Sc * INNERc];    // 2 MB, RoPE'd q, pre-scaled by 1/8 (exact)
__device__ float g_k[Bc * Sc * INNERc];    // 2 MB, RoPE'd k
__device__ float g_bn[Bc * Lc * Sc];       // dense[b,2l,n]/2  (added along n)
__device__ float g_bm[Bc * Lc * Sc];       // dense[b,2l+1,m]/2 (added along m)

// ---------------- f32x2 helpers ----------------
__device__ __forceinline__ ull fma2(ull a, ull b, ull c) {
    ull d;
    asm("fma.rn.f32x2 %0, %1, %2, %3;" : "=l"(d) : "l"(a), "l"(b), "l"(c));
    return d;
}
__device__ __forceinline__ ull add2(ull a, ull b) {
    ull d;
    asm("add.rn.f32x2 %0, %1, %2;" : "=l"(d) : "l"(a), "l"(b));
    return d;
}
__device__ __forceinline__ ull bcast2(float w) {
    ull d;
    unsigned int u = __float_as_uint(w);
    asm("mov.b64 %0, {%1, %1};" : "=l"(d) : "r"(u));
    return d;
}
__device__ __forceinline__ ull pack2(float lo, float hi) {
    ull d;
    asm("mov.b64 %0, {%1, %2};" : "=l"(d) : "f"(lo), "f"(hi));
    return d;
}
__device__ __forceinline__ void unpack2(ull v, float& lo, float& hi) {
    asm("mov.b64 {%0, %1}, %2;" : "=f"(lo), "=f"(hi) : "l"(v));
}
__device__ __forceinline__ float fast_sigmoid(float v) {
    float t;
    asm("tanh.approx.f32 %0, %1;" : "=f"(t) : "f"(v * 0.5f));
    return fmaf(t, 0.5f, 0.5f);
}

// ---------------- kernel 1: fused GEMM1+RoPE+bias-split  ||  constant writer ----
// blocks [0,256): GEMM1 rows (32 rows/block of the 8192 (b,s) rows)
// blocks [256,704): fully-causal-masked output tiles (tm>tn): constants only
__global__ void __launch_bounds__(256) phase1_fast_kernel(
    const float* __restrict__ x, const int* __restrict__ am,
    const float* __restrict__ w1, const float* __restrict__ b1,
    const float* __restrict__ w2, const float* __restrict__ b2,
    float* __restrict__ out)
{
    const size_t PROB_OFF = (size_t)Bc * Lc * Sc * Sc;   // 83886080
    int bid = blockIdx.x;
    int tid = threadIdx.x;

    __shared__ float xs[32][34];    // transposed tile: xs[kk][r]
    __shared__ float ws[32][192];   // ws[kk][c], c<128: w1, 128..167: w2, rest 0
    __shared__ float cs_s[32][32];  // cos/sin for this block's 32 rows
    __shared__ float sn_s[32][32];

    if (bid >= 256) {
        // -------- fast path: tm > tn => every element strictly below diagonal
        // logits = keep ? -NEG : -2*NEG  (exact: |raw| << ulp(1e12)); probs = 0
        int f = bid - 256;               // 0..447
        int b = f / 28;
        int p = f % 28;
        int tm = 1;
        while (p >= tm) { p -= tm; tm++; }   // tm in 1..7, tn = p < tm
        int tn = p;
        int m0 = tm * 64, n0 = tn * 64;
        int tx = tid & 15, ty = tid >> 4;
        const int* amb = am + b * Sc;
        int gn = n0 + tx * 4;
        int mn0 = amb[gn + 0], mn1 = amb[gn + 1], mn2 = amb[gn + 2], mn3 = amb[gn + 3];
        float4 lv[4];
        #pragma unroll
        for (int i = 0; i < 4; i++) {
            int mmv = amb[m0 + ty * 4 + i];
            lv[i].x = (mmv && mn0) ? -NEGF : -2.0f * NEGF;
            lv[i].y = (mmv && mn1) ? -NEGF : -2.0f * NEGF;
            lv[i].z = (mmv && mn2) ? -NEGF : -2.0f * NEGF;
            lv[i].w = (mmv && mn3) ? -NEGF : -2.0f * NEGF;
        }
        float4 z4 = make_float4(0.f, 0.f, 0.f, 0.f);
        float* p0 = out + (((size_t)(b * Lc)) * Sc + (m0 + ty * 4)) * (size_t)Sc + gn;
        for (int l = 0; l < Lc; l++) {
            #pragma unroll
            for (int i = 0; i < 4; i++) {
                float* pp = p0 + (size_t)i * Sc;
                __stcs(reinterpret_cast<float4*>(pp), lv[i]);
                __stcs(reinterpret_cast<float4*>(pp + PROB_OFF), z4);
            }
            p0 += (size_t)Sc * Sc;
        }
        return;
    }

    // -------- inline RoPE tables for this block's 32 rows (4 sincosf/thread)
    int row0 = bid * 32;
    #pragma unroll
    for (int t = 0; t < 4; t++) {
        int idx = tid + t * 256;            // 1024 = 32 rows x 32 freqs
        int r = idx >> 5, i = idx & 31;
        // freq_i = 10000^(-2 i / 64) = 2^(-i * log2(1e4)/32)
        float fq = exp2f(-(float)i * 0.41524101186092036f);
        float ang = (float)(row0 + r) * fq;
        float sv, cv;
        sincosf(ang, &sv, &cv);
        cs_s[r][i] = cv;
        sn_s[r][i] = sv;
    }

    // -------- GEMM1: out1[8192 x 192pad] = x[8192 x 768] @ [w1|w2|0]
    int ct = tid & 31;        // col thread (lane)
    int rt = tid >> 5;        // row thread 0..7
    int r0 = rt * 4;          // 4 rows per thread, as 2 f32x2 pairs

    ull acc[2][6];
    #pragma unroll
    for (int a = 0; a < 2; a++)
        #pragma unroll
        for (int j = 0; j < 6; j++) acc[a][j] = 0ull;

    for (int k0 = 0; k0 < Dc; k0 += 32) {
        #pragma unroll
        for (int t = 0; t < 4; t++) {
            int idx = tid + t * 256;        // 1024 = 32x32
            int r = idx >> 5, kk = idx & 31;
            xs[kk][r] = x[(size_t)(row0 + r) * Dc + k0 + kk];
        }
        #pragma unroll
        for (int t = 0; t < 24; t++) {
            int idx = tid + t * 256;        // 6144 = 32x192
            int kk = idx / 192, c = idx - kk * 192;
            float v;
            if (c < 128)      v = w1[(size_t)(k0 + kk) * 128 + c];
            else if (c < 168) v = w2[(size_t)(k0 + kk) * 40 + (c - 128)];
            else              v = 0.f;
            ws[kk][c] = v;
        }
        __syncthreads();
        #pragma unroll
        for (int kk = 0; kk < 32; kk++) {
            ull xa = *reinterpret_cast<const ull*>(&xs[kk][r0]);
            ull xb = *reinterpret_cast<const ull*>(&xs[kk][r0 + 2]);
            #pragma unroll
            for (int j = 0; j < 6; j++) {
                ull wp = bcast2(ws[kk][ct + 32 * j]);
                acc[0][j] = fma2(xa, wp, acc[0][j]);
                acc[1][j] = fma2(xb, wp, acc[1][j]);
            }
        }
        __syncthreads();
    }

    // -------- epilogue: bias, RoPE (cross-lane pair via shfl.xor 2), scatter
    #pragma unroll
    for (int j = 0; j < 6; j++) {
        int c = ct + 32 * j;
        float bias = 0.f;
        if (c < 128)      bias = b1[c];
        else if (c < 168) bias = b2[c - 128];
        #pragma unroll
        for (int rr = 0; rr < 4; rr++) {
            ull a = acc[rr >> 1][j];
            unsigned int u = (rr & 1) ? (unsigned int)(a >> 32) : (unsigned int)a;
            float v = __uint_as_float(u) + bias;
            float prt = __shfl_xor_sync(0xffffffffu, v, 2);  // col c ^ 2 partner
            int row = row0 + r0 + rr;
            int bb = row >> 9, s = row & 511;
            if (c < 128) {
                int i = c >> 2;
                float cs = cs_s[r0 + rr][i];
                float sn = sn_s[r0 + rr][i];
                float o = (c & 2) ? (v * cs + prt * sn) : (v * cs - prt * sn);
                if (c & 1) g_k[(size_t)row * 64 + (c >> 1)] = o;
                else       g_q[(size_t)row * 64 + (c >> 1)] = o * 0.125f;  // /8 folded, exact
            } else if (c < 168) {
                int cc = c - 128;
                float val = v * 0.5f;
                int l = cc >> 1;
                size_t o = ((size_t)bb * Lc + l) * Sc + s;
                if (cc & 1) g_bm[o] = val;
                else        g_bn[o] = val;
            }
        }
    }
}

// ---------------- kernel 2: base q.k^T tile + 10 L-slices of fused epilogue ----
// grid: x = 36 upper-tri tiles * 2 l-halves, y = batch
__global__ void __launch_bounds__(256) phase2_kernel(
    const int* __restrict__ am, float* __restrict__ out)
{
    __shared__ float qT[64][68];             // transposed: qT[kk][m]
    __shared__ float kT[64][68];
    __shared__ int   mMs[64], mNs[64];

    int bx = blockIdx.x;
    int b = blockIdx.y;
    int lh = bx & 1, tidx = bx >> 1;
    int tm = 0;
    { int t = tidx; while (t >= 8 - tm) { t -= 8 - tm; tm++; } tidx = t; }
    int tn = tm + tidx;
    int l0 = lh * 10;

    int tid = threadIdx.x;
    int m0 = tm * 64, n0 = tn * 64;
    const float* qb = g_q + (size_t)b * Sc * 64;
    const float* kb = g_k + (size_t)b * Sc * 64;

    #pragma unroll
    for (int t = 0; t < 16; t++) {
        int idx = tid + t * 256;             // 4096 = 64x64
        int r = idx >> 6, kk = idx & 63;
        qT[kk][r] = qb[(size_t)(m0 + r) * 64 + kk];
        kT[kk][r] = kb[(size_t)(n0 + r) * 64 + kk];
    }
    if (tid < 64) {
        mMs[tid] = am[b * Sc + m0 + tid];
        mNs[tid] = am[b * Sc + n0 + tid];
    }
    __syncthreads();

    int tx = tid & 15, ty = tid >> 4;
    int nl = tx * 4, ml = ty * 4;

    ull acc2[4][2];
    #pragma unroll
    for (int i = 0; i < 4; i++) { acc2[i][0] = 0ull; acc2[i][1] = 0ull; }

    #pragma unroll 4
    for (int kk = 0; kk < 64; kk++) {
        float4 qv = *reinterpret_cast<const float4*>(&qT[kk][ml]);
        float4 kv = *reinterpret_cast<const float4*>(&kT[kk][nl]);
        ull k01 = pack2(kv.x, kv.y);
        ull k23 = pack2(kv.z, kv.w);
        ull q0 = bcast2(qv.x), q1 = bcast2(qv.y), q2 = bcast2(qv.z), q3 = bcast2(qv.w);
        acc2[0][0] = fma2(q0, k01, acc2[0][0]); acc2[0][1] = fma2(q0, k23, acc2[0][1]);
        acc2[1][0] = fma2(q1, k01, acc2[1][0]); acc2[1][1] = fma2(q1, k23, acc2[1][1]);
        acc2[2][0] = fma2(q2, k01, acc2[2][0]); acc2[2][1] = fma2(q2, k23, acc2[2][1]);
        acc2[3][0] = fma2(q3, k01, acc2[3][0]); acc2[3][1] = fma2(q3, k23, acc2[3][1]);
    }
    // acc2 already = q.k / 8 (scale folded into g_q, exact power of 2)

    int mm[4], mn[4];
    #pragma unroll
    for (int i = 0; i < 4; i++) mm[i] = mMs[ml + i];
    #pragma unroll
    for (int j = 0; j < 4; j++) mn[j] = mNs[nl + j];

    float* probs = out + (size_t)Bc * Lc * Sc * Sc;
    int gm0 = m0 + ml, gn0 = n0 + nl;
    size_t rowbase = (((size_t)(b * Lc + l0)) * Sc + gm0) * (size_t)Sc + gn0;

    // direct L2 reads of bn/bm with a 1-deep software pipeline
    const float* bn_ptr = g_bn + ((size_t)b * Lc + l0) * Sc + n0 + nl;
    const float* bm_ptr = g_bm + ((size_t)b * Lc + l0) * Sc + m0 + ml;

    float4 bn_cur = __ldg(reinterpret_cast<const float4*>(bn_ptr));
    float4 bm_cur = __ldg(reinterpret_cast<const float4*>(bm_ptr));

    for (int l = 0; l < 10; l++) {
        float4 bn_nxt, bm_nxt;
        if (l < 9) {
            bn_nxt = __ldg(reinterpret_cast<const float4*>(bn_ptr + (size_t)(l + 1) * Sc));
            bm_nxt = __ldg(reinterpret_cast<const float4*>(bm_ptr + (size_t)(l + 1) * Sc));
        }
        ull bn01 = pack2(bn_cur.x, bn_cur.y);
        ull bn23 = pack2(bn_cur.z, bn_cur.w);
        float bmv[4] = {bm_cur.x, bm_cur.y, bm_cur.z, bm_cur.w};
        #pragma unroll
        for (int i = 0; i < 4; i++) {
            int gm = gm0 + i;
            ull bm2 = bcast2(bmv[i]);
            ull v01 = add2(add2(acc2[i][0], bn01), bm2);
            ull v23 = add2(add2(acc2[i][1], bn23), bm2);
            float v[4];
            unpack2(v01, v[0], v[1]);
            unpack2(v23, v[2], v[3]);
            float lv[4], pv[4];
            #pragma unroll
            for (int j = 0; j < 4; j++) {
                float xv = (mm[i] && mn[j]) ? v[j] : -NEGF;
                if (gm > gn0 + j) xv -= NEGF;       // strict lower triangle
                lv[j] = xv;
                pv[j] = fast_sigmoid(xv);
            }
            size_t o = rowbase + (size_t)i * Sc;
            __stcs(reinterpret_cast<float4*>(out + o),
                   make_float4(lv[0], lv[1], lv[2], lv[3]));
            __stcs(reinterpret_cast<float4*>(probs + o),
                   make_float4(pv[0], pv[1], pv[2], pv[3]));
        }
        bn_cur = bn_nxt;
        bm_cur = bm_nxt;
        rowbase += (size_t)Sc * Sc;
    }
}

// ---------------- launcher ----------------
extern "C" void kernel_launch(void* const* d_in, const int* in_sizes, int n_in,
                              void* d_out, int out_size) {
    (void)in_sizes; (void)n_in; (void)out_size;
    const float* x  = (const float*)d_in[0];
    const int*   am = (const int*)  d_in[1];
    const float* w1 = (const float*)d_in[2];
    const float* b1 = (const float*)d_in[3];
    const float* w2 = (const float*)d_in[4];
    const float* b2 = (const float*)d_in[5];
    float* out = (float*)d_out;

    phase1_fast_kernel<<<704, 256>>>(x, am, w1, b1, w2, b2, out);
    dim3 g2(72, 16);
    phase2_kernel<<<g2, 256>>>(am, out);
}